// round 12
// baseline (speedup 1.0000x reference)
#include <cuda_runtime.h>
#include <cuda_bf16.h>
#include <cuda_fp16.h>
#include <cstdint>

#define BATCH 8
#define SEQ   2048
#define DM    1024
#define DH    64
#define NTOK  (BATCH * SEQ)
#define ITILES 16

// ---------------- device scratch ----------------
__device__ __half g_W[3 * DH * DM];                // [mat*64+c][k], fp16
__device__ __half g_Q[NTOK * DH];                  // Q fp16
__device__ __half g_K[NTOK * DH];                  // K fp16
__device__ float  g_Vt[BATCH * DH * SEQ];          // V fp32, [b][d][i]
__device__ __half g_Vf[BATCH * DH * SEQ];          // V' = diag(c) V, fp16, [b][d][i]
__device__ float g_psum[BATCH * ITILES * SEQ];

// ---------------- helpers ----------------
__device__ __forceinline__ uint32_t s_u32(const void* p) {
    uint32_t a;
    asm("{ .reg .u64 t; cvta.to.shared.u64 t, %1; cvt.u32.u64 %0, t; }" : "=r"(a) : "l"(p));
    return a;
}
#define LDSM4(r0, r1, r2, r3, addr) \
    asm volatile("ldmatrix.sync.aligned.m8n8.x4.shared.b16 {%0,%1,%2,%3}, [%4];" \
                 : "=r"(r0), "=r"(r1), "=r"(r2), "=r"(r3) : "r"(addr))
#define CPA16(dst, src) \
    asm volatile("cp.async.cg.shared.global [%0], [%1], 16;" :: "r"(dst), "l"(src))
#define CPA_COMMIT() asm volatile("cp.async.commit_group;" ::: "memory")
#define CPA_WAIT1()  asm volatile("cp.async.wait_group 1;" ::: "memory")
#define CPA_WAIT0()  asm volatile("cp.async.wait_group 0;" ::: "memory")

__device__ __forceinline__ void mma_f16(float* c, const uint32_t* a, const uint32_t* b) {
    asm volatile(
        "mma.sync.aligned.m16n8k16.row.col.f32.f16.f16.f32 "
        "{%0,%1,%2,%3}, {%4,%5,%6,%7}, {%8,%9}, {%0,%1,%2,%3};"
        : "+f"(c[0]), "+f"(c[1]), "+f"(c[2]), "+f"(c[3])
        : "r"(a[0]), "r"(a[1]), "r"(a[2]), "r"(a[3]), "r"(b[0]), "r"(b[1]));
}
__device__ __forceinline__ uint32_t pk2(unsigned short a, unsigned short b) {
    return (uint32_t)a | ((uint32_t)b << 16);
}
__device__ __forceinline__ unsigned short h16(float v) {
    return __half_as_ushort(__float2half(v));
}

// ---------------- W -> fp16 transpose ----------------
__global__ __launch_bounds__(256) void split_w_kernel(
    const float* __restrict__ Wq, const float* __restrict__ Wk, const float* __restrict__ Wv) {
    int mt = blockIdx.y;
    const float* W = (mt == 0) ? Wq : (mt == 1) ? Wk : Wv;
    int idx = blockIdx.x * 256 + threadIdx.x;
    int k = idx >> 6, c = idx & 63;
    g_W[(mt * 64 + c) * DM + k] = __float2half(W[k * DH + c]);
}

// ---------------- fused QKV projection: 2-stage, single-fp16 ----------------
__global__ __launch_bounds__(512) void proj_kernel(
    const float* __restrict__ x, const float* __restrict__ bq,
    const float* __restrict__ bk, const float* __restrict__ bv) {
    extern __shared__ char smem[];
    const uint32_t sbase = s_u32(smem);
    const int tid = threadIdx.x, lane = tid & 31, w = tid >> 5;
    const int row0 = blockIdx.x * 128;
    const int bb = row0 >> 11, iloc = row0 & 2047;

    const int wm = w & 3, wn = w >> 2;
    float acc[2][6][4];
    #pragma unroll
    for (int i = 0; i < 2; i++)
        #pragma unroll
        for (int j = 0; j < 6; j++)
            #pragma unroll
            for (int q = 0; q < 4; q++) acc[i][j][q] = 0.f;

    const int xr_r = tid >> 2, xr_c = (tid & 3) * 16;

    auto ldx = [&](int kc, float4* xr) {
        const float4* src = (const float4*)(x + (size_t)(row0 + xr_r) * DM + kc * 64 + xr_c);
        xr[0] = src[0]; xr[1] = src[1]; xr[2] = src[2]; xr[3] = src[3];
    };
    auto convA = [&](const float4* xr, int st) {
        __half* A = (__half*)(smem + st * 46080);
        unsigned short hs[16];
        #pragma unroll
        for (int q = 0; q < 4; q++) {
            float4 v = xr[q];
            hs[q*4+0] = h16(v.x); hs[q*4+1] = h16(v.y);
            hs[q*4+2] = h16(v.z); hs[q*4+3] = h16(v.w);
        }
        uint4* dh = (uint4*)(A + xr_r * 72 + xr_c);
        dh[0] = make_uint4(pk2(hs[0],hs[1]), pk2(hs[2],hs[3]), pk2(hs[4],hs[5]), pk2(hs[6],hs[7]));
        dh[1] = make_uint4(pk2(hs[8],hs[9]), pk2(hs[10],hs[11]), pk2(hs[12],hs[13]), pk2(hs[14],hs[15]));
    };
    auto ldW = [&](int kc, int st) {
        uint32_t bw = sbase + st * 46080 + 18432;
        #pragma unroll
        for (int p = 0; p < 3; p++) {
            int lin = p * 512 + tid, r = lin >> 3, q = lin & 7;
            CPA16(bw + (uint32_t)(r * 144 + q * 16),
                  (const char*)g_W + ((size_t)r * DM + kc * 64) * 2 + q * 16);
        }
        CPA_COMMIT();
    };

    float4 xr[4];
    ldx(0, xr);
    ldW(0, 0);
    convA(xr, 0);
    CPA_WAIT0();
    __syncthreads();

    for (int c = 0; c < 16; c++) {
        const int cur = c & 1;
        if (c < 15) { ldx(c + 1, xr); ldW(c + 1, cur ^ 1); }

        const uint32_t S = sbase + cur * 46080;
        const uint32_t sA = S, sB = S + 18432;
        #pragma unroll
        for (int ks = 0; ks < 4; ks++) {
            const int k0 = ks * 16;
            uint32_t a[2][4];
            #pragma unroll
            for (int mf = 0; mf < 2; mf++) {
                uint32_t off = (uint32_t)((wm * 32 + mf * 16 + (lane & 15)) * 72 +
                                          k0 + ((lane >> 4) << 3)) * 2;
                LDSM4(a[mf][0], a[mf][1], a[mf][2], a[mf][3], sA + off);
            }
            uint32_t b[6][2];
            #pragma unroll
            for (int nb = 0; nb < 3; nb++) {
                uint32_t off = (uint32_t)((wn * 48 + nb * 16 + (lane & 7) + ((lane >> 4) << 3)) * 72 +
                                          k0 + (((lane >> 3) & 1) << 3)) * 2;
                LDSM4(b[2*nb][0], b[2*nb][1], b[2*nb+1][0], b[2*nb+1][1], sB + off);
            }
            #pragma unroll
            for (int mf = 0; mf < 2; mf++)
                #pragma unroll
                for (int nf = 0; nf < 6; nf++)
                    mma_f16(acc[mf][nf], a[mf], b[nf]);
        }
        if (c < 15) { convA(xr, cur ^ 1); CPA_WAIT0(); }
        __syncthreads();
    }

    // epilogue: Q, K fp16 direct; V staged fp32 transposed
    float* sV = (float*)smem;     // [64][132] fp32
    #pragma unroll
    for (int mf = 0; mf < 2; mf++)
        #pragma unroll
        for (int nf = 0; nf < 6; nf++) {
            int gc = wn * 48 + nf * 8 + (lane & 3) * 2;
            int mt = gc >> 6, cm = gc & 63;
            int r0 = wm * 32 + mf * 16 + (lane >> 2);
            #pragma unroll
            for (int h = 0; h < 2; h++) {
                int rl = r0 + h * 8;
                float v0 = acc[mf][nf][h * 2 + 0], v1 = acc[mf][nf][h * 2 + 1];
                if (mt == 0) {
                    size_t o = (size_t)(row0 + rl) * DH + cm;
                    *(uint32_t*)(g_Q + o) = pk2(h16(v0 + bq[cm]), h16(v1 + bq[cm + 1]));
                } else if (mt == 1) {
                    size_t o = (size_t)(row0 + rl) * DH + cm;
                    *(uint32_t*)(g_K + o) = pk2(h16(v0 + bk[cm]), h16(v1 + bk[cm + 1]));
                } else {
                    sV[cm * 132 + rl]       = v0 + bv[cm];
                    sV[(cm + 1) * 132 + rl] = v1 + bv[cm + 1];
                }
            }
        }
    __syncthreads();
    #pragma unroll
    for (int p = 0; p < 4; p++) {
        int lin = p * 512 + tid, r = lin >> 5, q4 = lin & 31;
        *(float4*)(g_Vt + (size_t)(bb * 64 + r) * SEQ + iloc + q4 * 4) =
            *(float4*)(sV + r * 132 + q4 * 4);
    }
}

// ---------------- colsum pass: S = QK^T/8, exp, per-tile column sums (NO E store) ----------------
// grid (16,16,8), block 256. smem: Q,K [128][72]h (36864 B); reused as Est fp16 pitch 136.
__global__ __launch_bounds__(256) void colsum_kernel() {
    extern __shared__ char smem[];
    __shared__ float sred[256];
    const int tid = threadIdx.x, lane = tid & 31, w = tid >> 5;
    const int jt = blockIdx.x, it = blockIdx.y, bb = blockIdx.z;
    const int i0 = it * 128, j0 = jt * 128;
    const uint32_t sbase = s_u32(smem);

    {
        const __half* src[2] = { g_Q, g_K };
        #pragma unroll
        for (int a = 0; a < 2; a++) {
            const int rb = bb * SEQ + ((a == 0) ? i0 : j0);
            #pragma unroll
            for (int p = 0; p < 4; p++) {
                int lin = p * 256 + tid, r = lin >> 3, q = lin & 7;
                CPA16(sbase + a * 18432 + (uint32_t)(r * 144 + q * 16),
                      (const char*)src[a] + ((size_t)(rb + r) * DH) * 2 + q * 16);
            }
        }
        CPA_COMMIT(); CPA_WAIT0();
    }
    __syncthreads();

    const uint32_t sQ = sbase, sK = sbase + 18432;
    const int wm = w & 1, wn = w >> 1;
    float acc[4][4][4];
    #pragma unroll
    for (int i = 0; i < 4; i++)
        #pragma unroll
        for (int j = 0; j < 4; j++)
            #pragma unroll
            for (int q = 0; q < 4; q++) acc[i][j][q] = 0.f;

    #pragma unroll
    for (int ks = 0; ks < 4; ks++) {
        const int k0 = ks * 16;
        uint32_t a[4][4];
        #pragma unroll
        for (int mf = 0; mf < 4; mf++) {
            uint32_t off = (uint32_t)((wm * 64 + mf * 16 + (lane & 15)) * 72 +
                                      k0 + ((lane >> 4) << 3)) * 2;
            LDSM4(a[mf][0], a[mf][1], a[mf][2], a[mf][3], sQ + off);
        }
        uint32_t b[4][2];
        #pragma unroll
        for (int nb = 0; nb < 2; nb++) {
            uint32_t off = (uint32_t)((wn * 32 + nb * 16 + (lane & 7) + ((lane >> 4) << 3)) * 72 +
                                      k0 + (((lane >> 3) & 1) << 3)) * 2;
            LDSM4(b[2*nb][0], b[2*nb][1], b[2*nb+1][0], b[2*nb+1][1], sK + off);
        }
        #pragma unroll
        for (int mf = 0; mf < 4; mf++)
            #pragma unroll
            for (int nf = 0; nf < 4; nf++)
                mma_f16(acc[mf][nf], a[mf], b[nf]);
    }
    __syncthreads();

    // stage E = exp(S/8) as fp16 (identical rounding to attn pass) and column-reduce
    __half* Est = (__half*)smem;
    #pragma unroll
    for (int mf = 0; mf < 4; mf++)
        #pragma unroll
        for (int nf = 0; nf < 4; nf++) {
            int col = wn * 32 + nf * 8 + (lane & 3) * 2;
            int r0 = wm * 64 + mf * 16 + (lane >> 2);
            #pragma unroll
            for (int h = 0; h < 2; h++) {
                float e0 = __expf(0.125f * acc[mf][nf][h * 2 + 0]);
                float e1 = __expf(0.125f * acc[mf][nf][h * 2 + 1]);
                *(__half2*)(Est + (r0 + h * 8) * 136 + col) = __floats2half2_rn(e0, e1);
            }
        }
    __syncthreads();
    {
        int col = tid & 127, hf = tid >> 7;
        float s = 0.f;
        #pragma unroll 8
        for (int i = 0; i < 64; i++) s += __half2float(Est[(hf * 64 + i) * 136 + col]);
        sred[tid] = s;
        __syncthreads();
        if (tid < 128)
            g_psum[(bb * ITILES + it) * SEQ + j0 + tid] = sred[tid] + sred[tid + 128];
    }
}

// ---------------- fused merge psums -> c, V' = c*V -> fp16 (parallel) ----------------
// grid (16, 8), block 256. Block owns i-range [bx*128, bx*128+128) for all 64 d.
__global__ __launch_bounds__(256) void merge_scale_kernel() {
    __shared__ float sc[128];
    const int tid = threadIdx.x;
    const int bx = blockIdx.x, bb = blockIdx.y;
    const int ibase = bx * 128;
    if (tid < 128) {
        int j = ibase + tid;
        float s = 0.f;
        #pragma unroll
        for (int it = 0; it < ITILES; it++)
            s += g_psum[(bb * ITILES + it) * SEQ + j];
        sc[tid] = 1.0f / s;
    }
    __syncthreads();
    // scale: 64 d x 128 i = 8192 elems = 2048 float4 / 256 thr = 8 each
    #pragma unroll
    for (int p = 0; p < 8; p++) {
        int lin = p * 256 + tid, d = lin >> 5, q = lin & 31;   // q: float4 within row
        size_t idx = (size_t)(bb * 64 + d) * SEQ + ibase + q * 4;
        float4 v = *(const float4*)(g_Vt + idx);
        float c0 = sc[q*4], c1 = sc[q*4+1], c2 = sc[q*4+2], c3 = sc[q*4+3];
        __half2 lo = __floats2half2_rn(v.x * c0, v.y * c1);
        __half2 hi = __floats2half2_rn(v.z * c2, v.w * c3);
        *(uint2*)(g_Vf + idx) = make_uint2(
            pk2(__half_as_ushort(__low2half(lo)), __half_as_ushort(__high2half(lo))),
            pk2(__half_as_ushort(__low2half(hi)), __half_as_ushort(__high2half(hi))));
    }
}

// ---------------- fused attention: O = exp(QK^T/8) @ V'  (no E materialization) ----------------
// grid (16,8), block 256 (8 warps). i-tile 128; 16 j-chunks of 128.
// smem: sQ @0 (18432) | sP @18432 (34816) | sK[2] @53248 (18432 ea) | sV[2] @90112 (17408 ea)
// total 124928. Epilogue Ost f32 [128][68] reuses sP region.
__global__ __launch_bounds__(256) void attn_kernel(float* __restrict__ out) {
    extern __shared__ char smem[];
    const int tid = threadIdx.x, lane = tid & 31, w = tid >> 5;
    const int it = blockIdx.x, bb = blockIdx.y;
    const int i0 = it * 128;
    const uint32_t sbase = s_u32(smem);
    const uint32_t sQ = sbase, sP = sbase + 18432;
    const uint32_t sKb = sbase + 53248, sVb = sbase + 90112;

    // S-MMA warp tiling: wm1 rows of 64, wn1 cols of 32
    const int wm1 = w & 1, wn1 = w >> 1;
    // O-MMA warp tiling: wm2 rows of 32 (4 groups), wn2 cols of 32 (2 groups)
    const int wm2 = w & 3, wn2 = w >> 2;

    float accO[2][4][4];
    #pragma unroll
    for (int i = 0; i < 2; i++)
        #pragma unroll
        for (int j = 0; j < 4; j++)
            #pragma unroll
            for (int q = 0; q < 4; q++) accO[i][j][q] = 0.f;

    auto issueKV = [&](int c) {
        const int buf = c & 1;
        const int j0 = c * 128;
        #pragma unroll
        for (int p = 0; p < 4; p++) {            // K: 128 rows x 128B
            int lin = p * 256 + tid, r = lin >> 3, q = lin & 7;
            CPA16(sKb + buf * 18432 + (uint32_t)(r * 144 + q * 16),
                  (const char*)g_K + ((size_t)(bb * SEQ + j0 + r) * DH) * 2 + q * 16);
        }
        #pragma unroll
        for (int p = 0; p < 4; p++) {            // V': 64 rows(d) x 256B
            int lin = p * 256 + tid, r = lin >> 4, q = lin & 15;
            CPA16(sVb + buf * 17408 + (uint32_t)(r * 272 + q * 16),
                  (const char*)g_Vf + ((size_t)(bb * 64 + r) * SEQ + j0) * 2 + q * 16);
        }
    };

    // prologue: Q + KV(0) in group 0; KV(1) in group 1
    #pragma unroll
    for (int p = 0; p < 4; p++) {                // Q: 128 rows x 128B
        int lin = p * 256 + tid, r = lin >> 3, q = lin & 7;
        CPA16(sQ + (uint32_t)(r * 144 + q * 16),
              (const char*)g_Q + ((size_t)(bb * SEQ + i0 + r) * DH) * 2 + q * 16);
    }
    issueKV(0); CPA_COMMIT();
    issueKV(1); CPA_COMMIT();

    for (int c = 0; c < 16; c++) {
        if (c < 15) { CPA_WAIT1(); } else { CPA_WAIT0(); }
        __syncthreads();

        const uint32_t sK = sKb + (c & 1) * 18432;
        const uint32_t sV = sVb + (c & 1) * 17408;

        // ---- S = Q K^T ----
        float accS[4][4][4];
        #pragma unroll
        for (int i = 0; i < 4; i++)
            #pragma unroll
            for (int j = 0; j < 4; j++)
                #pragma unroll
                for (int q = 0; q < 4; q++) accS[i][j][q] = 0.f;
        #pragma unroll
        for (int ks = 0; ks < 4; ks++) {
            const int k0 = ks * 16;
            uint32_t a[4][4];
            #pragma unroll
            for (int mf = 0; mf < 4; mf++) {
                uint32_t off = (uint32_t)((wm1 * 64 + mf * 16 + (lane & 15)) * 72 +
                                          k0 + ((lane >> 4) << 3)) * 2;
                LDSM4(a[mf][0], a[mf][1], a[mf][2], a[mf][3], sQ + off);
            }
            uint32_t b[4][2];
            #pragma unroll
            for (int nb = 0; nb < 2; nb++) {
                uint32_t off = (uint32_t)((wn1 * 32 + nb * 16 + (lane & 7) + ((lane >> 4) << 3)) * 72 +
                                          k0 + (((lane >> 3) & 1) << 3)) * 2;
                LDSM4(b[2*nb][0], b[2*nb][1], b[2*nb+1][0], b[2*nb+1][1], sK + off);
            }
            #pragma unroll
            for (int mf = 0; mf < 4; mf++)
                #pragma unroll
                for (int nf = 0; nf < 4; nf++)
                    mma_f16(accS[mf][nf], a[mf], b[nf]);
        }
        // ---- P = exp(S/8) -> sP (fp16, pitch 136) ----
        #pragma unroll
        for (int mf = 0; mf < 4; mf++)
            #pragma unroll
            for (int nf = 0; nf < 4; nf++) {
                int col = wn1 * 32 + nf * 8 + (lane & 3) * 2;
                int r0 = wm1 * 64 + mf * 16 + (lane >> 2);
                #pragma unroll
                for (int h = 0; h < 2; h++) {
                    float e0 = __expf(0.125f * accS[mf][nf][h * 2 + 0]);
                    float e1 = __expf(0.125f * accS[mf][nf][h * 2 + 1]);
                    *(__half2*)((char*)smem + 18432 + ((r0 + h * 8) * 136 + col) * 2) =
                        __floats2half2_rn(e0, e1);
                }
            }
        __syncthreads();
        // ---- O += P V'^T ----
        #pragma unroll
        for (int ks = 0; ks < 8; ks++) {
            const int k0 = ks * 16;
            uint32_t a[2][4];
            #pragma unroll
            for (int mf = 0; mf < 2; mf++) {
                uint32_t off = (uint32_t)((wm2 * 32 + mf * 16 + (lane & 15)) * 136 +
                                          k0 + ((lane >> 4) << 3)) * 2;
                LDSM4(a[mf][0], a[mf][1], a[mf][2], a[mf][3], sP + off);
            }
            uint32_t b[4][2];
            #pragma unroll
            for (int nb = 0; nb < 2; nb++) {
                uint32_t off = (uint32_t)((wn2 * 32 + nb * 16 + (lane & 7) + ((lane >> 4) << 3)) * 136 +
                                          k0 + (((lane >> 3) & 1) << 3)) * 2;
                LDSM4(b[2*nb][0], b[2*nb][1], b[2*nb+1][0], b[2*nb+1][1], sV + off);
            }
            #pragma unroll
            for (int mf = 0; mf < 2; mf++)
                #pragma unroll
                for (int nf = 0; nf < 4; nf++)
                    mma_f16(accO[mf][nf], a[mf], b[nf]);
        }
        __syncthreads();
        if (c + 2 < 16) { issueKV(c + 2); CPA_COMMIT(); }
    }

    // epilogue: stage O f32 (pitch 68) in sP region, coalesced store
    float* Ost = (float*)((char*)smem + 18432);
    #pragma unroll
    for (int mf = 0; mf < 2; mf++)
        #pragma unroll
        for (int nf = 0; nf < 4; nf++) {
            int col = wn2 * 32 + nf * 8 + (lane & 3) * 2;
            int r0 = wm2 * 32 + mf * 16 + (lane >> 2);
            #pragma unroll
            for (int h = 0; h < 2; h++) {
                Ost[(r0 + h * 8) * 68 + col]     = accO[mf][nf][h * 2 + 0];
                Ost[(r0 + h * 8) * 68 + col + 1] = accO[mf][nf][h * 2 + 1];
            }
        }
    __syncthreads();
    #pragma unroll
    for (int p = 0; p < 8; p++) {
        int lin = p * 256 + tid, r = lin >> 4, c4 = lin & 15;
        *(float4*)(out + ((size_t)(bb * SEQ + i0 + r)) * DH + c4 * 4) =
            *(float4*)(Ost + r * 68 + c4 * 4);
    }
}

// ---------------- launch ----------------
extern "C" void kernel_launch(void* const* d_in, const int* in_sizes, int n_in,
                              void* d_out, int out_size)
{
    const float* x  = (const float*)d_in[0];
    const float* Wq = (const float*)d_in[1];
    const float* bq = (const float*)d_in[2];
    const float* Wk = (const float*)d_in[3];
    const float* bk = (const float*)d_in[4];
    const float* Wv = (const float*)d_in[5];
    const float* bv = (const float*)d_in[6];
    float* out = (float*)d_out;

    cudaFuncSetAttribute(proj_kernel,   cudaFuncAttributeMaxDynamicSharedMemorySize, 92160);
    cudaFuncSetAttribute(colsum_kernel, cudaFuncAttributeMaxDynamicSharedMemorySize, 36864);
    cudaFuncSetAttribute(attn_kernel,   cudaFuncAttributeMaxDynamicSharedMemorySize, 124928);

    split_w_kernel<<<dim3(256, 3), 256>>>(Wq, Wk, Wv);
    proj_kernel<<<128, 512, 92160>>>(x, bq, bk, bv);
    colsum_kernel<<<dim3(16, 16, 8), 256, 36864>>>();
    merge_scale_kernel<<<dim3(16, 8), 256>>>();
    attn_kernel<<<dim3(16, 8), 256, 124928>>>(out);   // 16 i-tiles x 8 batches
}